// round 3
// baseline (speedup 1.0000x reference)
#include <cuda_runtime.h>

#define BATCH 8
#define H 8
#define L 1024
#define DK 64
#define BH 64            // BATCH*H
#define NPOS 65536       // BH*L
#define TTERMS 12
#define NT (TTERMS + 1)
#define CTX_ELEMS (BH * L * DK)   // 4194304

// -------- scratch (device globals; no runtime allocation) --------
__device__ float g_Qp[NPOS];
__device__ float g_Kp[NPOS];
__device__ float g_y[4][NPOS];
__device__ float g_stats[4][H][2];   // sum, sumsq per (branch, channel)
__device__ float g_scale[4][H];
__device__ float g_shift[4][H];
__device__ float g_catq[2 * NPOS];   // [q0 ; q1] contiguous
__device__ float g_catk[2 * NPOS];   // [k0 ; k1] contiguous
__device__ float g_Qm[NPOS];
__device__ float g_Km[NPOS];
__device__ float g_M[BH][NT * DK];   // moments M_t/t!  (t = 0..12)
__device__ float g_cscale;

__constant__ float c_invfact[NT] = {
    1.0f, 1.0f, 0.5f, 1.0f / 6.0f, 1.0f / 24.0f, 1.0f / 120.0f,
    1.0f / 720.0f, 1.0f / 5040.0f, 1.0f / 40320.0f, 1.0f / 362880.0f,
    1.0f / 3628800.0f, 1.0f / 39916800.0f, 1.0f / 479001600.0f};

// -------- K0: zero the atomic-accumulated stats every launch --------
__global__ void k0_zero() {
    int t = threadIdx.x;
    if (t < 4 * H * 2) ((float*)g_stats)[t] = 0.0f;
}

// -------- K1: Qp = Q . wq, Kp = K . wk (warp per output) --------
__global__ void k1_proj(const float* __restrict__ Q, const float* __restrict__ K,
                        const float* __restrict__ wq, const float* __restrict__ wk) {
    int warp = (blockIdx.x * blockDim.x + threadIdx.x) >> 5;
    int lane = threadIdx.x & 31;
    const float* src;
    const float* w;
    float* dst;
    int i;
    if (warp < NPOS) { src = Q; w = wq; dst = g_Qp; i = warp; }
    else             { src = K; w = wk; dst = g_Kp; i = warp - NPOS; }
    const float* p = src + (size_t)i * DK;
    float s = p[lane] * __ldg(w + lane) + p[lane + 32] * __ldg(w + lane + 32);
#pragma unroll
    for (int off = 16; off; off >>= 1) s += __shfl_down_sync(0xffffffffu, s, off);
    if (lane == 0) dst[i] = s;
}

// -------- K2: Conv1d(H->H, F) + bias, accumulate BN stats --------
// grid (o=8, b=8, which=2); 128 threads; each thread owns 8 contiguous l
template <int F>
__global__ void k2_conv(const float* __restrict__ cwA, const float* __restrict__ cbA,
                        const float* __restrict__ cwB, const float* __restrict__ cbB,
                        int brA, int brB) {
    const int pad = F / 2;
    int o = blockIdx.x, b = blockIdx.y, which = blockIdx.z;
    const float* cw = which ? cwB : cwA;
    const float* cb = which ? cbB : cbA;
    int br = which ? brB : brA;
    const float* x = (br < 2) ? g_Qp : g_Kp;

    __shared__ float wsh[H * F];
    int tid = threadIdx.x;
    if (tid < H * F) wsh[tid] = cw[o * (H * F) + tid];
    __syncthreads();

    int l0 = tid * 8;
    float bias = __ldg(cb + o);
    float acc[8];
#pragma unroll
    for (int j = 0; j < 8; j++) acc[j] = bias;

    const float* xb = x + b * (H * L);
#pragma unroll
    for (int i = 0; i < H; i++) {
        float xr[8 + F - 1];
#pragma unroll
        for (int m = 0; m < 8 + F - 1; m++) {
            int li = l0 + m - pad;
            xr[m] = (li >= 0 && li < L) ? xb[i * L + li] : 0.0f;
        }
#pragma unroll
        for (int f = 0; f < F; f++) {
            float wv = wsh[i * F + f];
#pragma unroll
            for (int j = 0; j < 8; j++) acc[j] += xr[j + f] * wv;
        }
    }

    float s1 = 0.0f, s2 = 0.0f;
#pragma unroll
    for (int j = 0; j < 8; j++) {
        g_y[br][b * (H * L) + o * L + l0 + j] = acc[j];
        s1 += acc[j];
        s2 += acc[j] * acc[j];
    }
#pragma unroll
    for (int off = 16; off; off >>= 1) {
        s1 += __shfl_down_sync(0xffffffffu, s1, off);
        s2 += __shfl_down_sync(0xffffffffu, s2, off);
    }
    __shared__ float red1[4], red2[4];
    int wi = tid >> 5, ln = tid & 31;
    if (ln == 0) { red1[wi] = s1; red2[wi] = s2; }
    __syncthreads();
    if (tid == 0) {
        atomicAdd(&g_stats[br][o][0], red1[0] + red1[1] + red1[2] + red1[3]);
        atomicAdd(&g_stats[br][o][1], red2[0] + red2[1] + red2[2] + red2[3]);
    }
}

// -------- K3: finalize BN affine, compute c = dot(wbq,wbk)/8 --------
__global__ void k3_final(const float* __restrict__ g0, const float* __restrict__ be0,
                         const float* __restrict__ g1, const float* __restrict__ be1,
                         const float* __restrict__ g2, const float* __restrict__ be2,
                         const float* __restrict__ g3, const float* __restrict__ be3,
                         const float* __restrict__ wbq, const float* __restrict__ wbk) {
    int t = threadIdx.x;
    if (t < 32) {
        int br = t >> 3, o = t & 7;
        const float* gg;
        const float* bb;
        if (br == 0) { gg = g0; bb = be0; }
        else if (br == 1) { gg = g1; bb = be1; }
        else if (br == 2) { gg = g2; bb = be2; }
        else { gg = g3; bb = be3; }
        float n = (float)(BATCH * L);
        float mu = g_stats[br][o][0] / n;
        float var = g_stats[br][o][1] / n - mu * mu;
        float sc = gg[o] / sqrtf(var + 1e-5f);
        g_scale[br][o] = sc;
        g_shift[br][o] = bb[o] - mu * sc;
    }
    if (t == 32) {
        float s = 0.0f;
        for (int d = 0; d < DK; d++) s += wbq[d] * wbk[d];
        g_cscale = s * 0.125f;  // 1/sqrt(64)
    }
}

// -------- K4: BN affine + row softmax over L, write into cat buffers --------
// grid (bh=64, br=4); 256 threads, 4 elems each
__global__ void k4_softmax() {
    int bh = blockIdx.x, br = blockIdx.y;
    int o = bh & 7;
    int tid = threadIdx.x;
    const float* y = &g_y[br][bh * L];
    float sc = g_scale[br][o], sh = g_shift[br][o];
    float v[4];
    float mx = -1e30f;
#pragma unroll
    for (int j = 0; j < 4; j++) {
        v[j] = y[tid + 256 * j] * sc + sh;
        mx = fmaxf(mx, v[j]);
    }
    __shared__ float red[8];
#pragma unroll
    for (int off = 16; off; off >>= 1) mx = fmaxf(mx, __shfl_xor_sync(0xffffffffu, mx, off));
    int wi = tid >> 5, ln = tid & 31;
    if (ln == 0) red[wi] = mx;
    __syncthreads();
    mx = red[0];
#pragma unroll
    for (int i = 1; i < 8; i++) mx = fmaxf(mx, red[i]);

    float s = 0.0f;
#pragma unroll
    for (int j = 0; j < 4; j++) {
        v[j] = __expf(v[j] - mx);
        s += v[j];
    }
    __syncthreads();
#pragma unroll
    for (int off = 16; off; off >>= 1) s += __shfl_xor_sync(0xffffffffu, s, off);
    if (ln == 0) red[wi] = s;
    __syncthreads();
    float tot = red[0];
#pragma unroll
    for (int i = 1; i < 8; i++) tot += red[i];
    float inv = 1.0f / tot;

    float* dst;
    if (br == 0) dst = &g_catq[bh * L];
    else if (br == 1) dst = &g_catq[NPOS + bh * L];
    else if (br == 2) dst = &g_catk[bh * L];
    else dst = &g_catk[NPOS + bh * L];
#pragma unroll
    for (int j = 0; j < 4; j++) dst[tid + 256 * j] = v[j] * inv;
}

// -------- K5a: torch-faithful cat/reshape max --------
__global__ void k5a_max() {
    int i = blockIdx.x * blockDim.x + threadIdx.x;
    if (i < NPOS) {
        g_Qm[i] = fmaxf(g_catq[2 * i], g_catq[2 * i + 1]);
        g_Km[i] = fmaxf(g_catk[2 * i], g_catk[2 * i + 1]);
    }
}

// -------- K5b: moments M_t[d] = sum_k Km[k]^t * V[k,d] / t! --------
// grid 64 (bh); 256 threads = 4 k-groups x 64 d
__global__ void k5b_moments(const float* __restrict__ V) {
    int bh = blockIdx.x;
    int tid = threadIdx.x;
    int kg = tid >> 6, d = tid & 63;
    float acc[NT];
#pragma unroll
    for (int t = 0; t < NT; t++) acc[t] = 0.0f;
    const float* vb = V + (size_t)bh * L * DK;
    const float* km = g_Km + bh * L;
    for (int j = 0; j < 256; j++) {
        int k = kg * 256 + j;
        float kv = __ldg(km + k);
        float v = vb[k * DK + d];
        float kv2 = kv * kv;
        float pe = v, po = v * kv;   // two independent power chains
        acc[0] += pe;
        acc[1] += po;
#pragma unroll
        for (int t = 2; t < NT; t += 2) {
            pe *= kv2;
            acc[t] += pe;
            if (t + 1 < NT) {
                po *= kv2;
                acc[t + 1] += po;
            }
        }
    }
    __shared__ float red[4][NT][DK];
#pragma unroll
    for (int t = 0; t < NT; t++) red[kg][t][d] = acc[t];
    __syncthreads();
    if (kg == 0) {
#pragma unroll
        for (int t = 0; t < NT; t++) {
            float s = red[0][t][d] + red[1][t][d] + red[2][t][d] + red[3][t][d];
            g_M[bh][t * DK + d] = s * c_invfact[t];
        }
    }
}

// -------- K6: attn rows (exp + normalize + store) and context via Horner --------
// grid (qblock=128, bh=64); 256 threads = 8 warps, 1 q-row per warp
__global__ void __launch_bounds__(256) k6_main(float* __restrict__ out) {
    int bh = blockIdx.y;
    int tid = threadIdx.x;
    __shared__ float sKm[L];
    __shared__ float sM[NT * DK];
    for (int i = tid; i < L; i += 256) sKm[i] = g_Km[bh * L + i];
    for (int i = tid; i < NT * DK; i += 256) sM[i] = g_M[bh][i];
    __syncthreads();

    int wi = tid >> 5, lane = tid & 31;
    int q = blockIdx.x * 8 + wi;
    float a = g_Qm[bh * L + q] * g_cscale;

    float E[8][4];
    float z = 0.0f;
#pragma unroll
    for (int j = 0; j < 8; j++) {
        float4 kmv = ((const float4*)sKm)[j * 32 + lane];
        E[j][0] = __expf(a * kmv.x);
        E[j][1] = __expf(a * kmv.y);
        E[j][2] = __expf(a * kmv.z);
        E[j][3] = __expf(a * kmv.w);
        z += (E[j][0] + E[j][1]) + (E[j][2] + E[j][3]);
    }
#pragma unroll
    for (int off = 16; off; off >>= 1) z += __shfl_xor_sync(0xffffffffu, z, off);
    float invz = 1.0f / z;

    float* attn = out + CTX_ELEMS + ((size_t)bh * L + q) * L;
#pragma unroll
    for (int j = 0; j < 8; j++) {
        float4 o4;
        o4.x = E[j][0] * invz;
        o4.y = E[j][1] * invz;
        o4.z = E[j][2] * invz;
        o4.w = E[j][3] * invz;
        ((float4*)attn)[j * 32 + lane] = o4;
    }

    float* ctx = out + ((size_t)bh * L + q) * DK;
#pragma unroll
    for (int dd = 0; dd < 2; dd++) {
        int d = lane + dd * 32;
        float num = sM[TTERMS * DK + d];
#pragma unroll
        for (int t = TTERMS - 1; t >= 0; t--) num = num * a + sM[t * DK + d];
        ctx[d] = num * invz;
    }
}

extern "C" void kernel_launch(void* const* d_in, const int* in_sizes, int n_in,
                              void* d_out, int out_size) {
    (void)in_sizes;
    (void)n_in;
    (void)out_size;
    const float* Q = (const float*)d_in[0];
    const float* K = (const float*)d_in[1];
    const float* V = (const float*)d_in[2];
    // d_in[3] = attn_mask (unused, faithful to reference)
    const float* wq = (const float*)d_in[4];
    const float* wk = (const float*)d_in[5];
    const float* wbq = (const float*)d_in[6];
    const float* wbk = (const float*)d_in[7];
    const float* cq3_w = (const float*)d_in[8];
    const float* cq3_b = (const float*)d_in[9];
    const float* cq9_w = (const float*)d_in[10];
    const float* cq9_b = (const float*)d_in[11];
    const float* ck3_w = (const float*)d_in[12];
    const float* ck3_b = (const float*)d_in[13];
    const float* ck9_w = (const float*)d_in[14];
    const float* ck9_b = (const float*)d_in[15];
    const float* bnq3_g = (const float*)d_in[16];
    const float* bnq3_b = (const float*)d_in[17];
    const float* bnq9_g = (const float*)d_in[18];
    const float* bnq9_b = (const float*)d_in[19];
    const float* bnk3_g = (const float*)d_in[20];
    const float* bnk3_b = (const float*)d_in[21];
    const float* bnk9_g = (const float*)d_in[22];
    const float* bnk9_b = (const float*)d_in[23];
    float* out = (float*)d_out;

    k0_zero<<<1, 64>>>();
    k1_proj<<<(2 * NPOS) / 8, 256>>>(Q, K, wq, wk);
    k2_conv<3><<<dim3(8, 8, 2), 128>>>(cq3_w, cq3_b, ck3_w, ck3_b, 0, 2);
    k2_conv<9><<<dim3(8, 8, 2), 128>>>(cq9_w, cq9_b, ck9_w, ck9_b, 1, 3);
    k3_final<<<1, 64>>>(bnq3_g, bnq3_b, bnq9_g, bnq9_b,
                        bnk3_g, bnk3_b, bnk9_g, bnk9_b, wbq, wbk);
    k4_softmax<<<dim3(BH, 4), 256>>>();
    k5a_max<<<NPOS / 256, 256>>>();
    k5b_moments<<<BH, 256>>>(V);
    k6_main<<<dim3(L / 8, BH), 256>>>(out);
}

// round 7
// speedup vs baseline: 1.5454x; 1.5454x over previous
#include <cuda_runtime.h>

#define BATCH 8
#define H 8
#define L 1024
#define DK 64
#define BH 64            // BATCH*H
#define NPOS 65536       // BH*L
#define TTERMS 12
#define NT (TTERMS + 1)
#define CTX_ELEMS (BH * L * DK)   // 4194304

// -------- scratch (device globals; no runtime allocation) --------
__device__ float g_Qp[NPOS];
__device__ float g_Kp[NPOS];
__device__ float g_y[4][NPOS];
__device__ float2 g_part[4][H][BATCH];   // per-block BN partials (no atomics)
__device__ float g_scale[4][H];
__device__ float g_shift[4][H];
__device__ float g_Qm[NPOS];
__device__ float g_Km[NPOS];
__device__ float g_Mp[4][BH][NT * DK];   // k-split moment partials (incl 1/t!)
__device__ float g_cscale;

__constant__ float c_invfact[NT] = {
    1.0f, 1.0f, 0.5f, 1.0f / 6.0f, 1.0f / 24.0f, 1.0f / 120.0f,
    1.0f / 720.0f, 1.0f / 5040.0f, 1.0f / 40320.0f, 1.0f / 362880.0f,
    1.0f / 3628800.0f, 1.0f / 39916800.0f, 1.0f / 479001600.0f};

// -------- K1: Qp = Q . wq, Kp = K . wk (warp per output) --------
__global__ void k1_proj(const float* __restrict__ Q, const float* __restrict__ K,
                        const float* __restrict__ wq, const float* __restrict__ wk) {
    int warp = (blockIdx.x * blockDim.x + threadIdx.x) >> 5;
    int lane = threadIdx.x & 31;
    const float* src;
    const float* w;
    float* dst;
    int i;
    if (warp < NPOS) { src = Q; w = wq; dst = g_Qp; i = warp; }
    else             { src = K; w = wk; dst = g_Kp; i = warp - NPOS; }
    const float* p = src + (size_t)i * DK;
    float s = p[lane] * __ldg(w + lane) + p[lane + 32] * __ldg(w + lane + 32);
#pragma unroll
    for (int off = 16; off; off >>= 1) s += __shfl_down_sync(0xffffffffu, s, off);
    if (lane == 0) dst[i] = s;
}

// -------- K2: all 4 Conv1d branches in one launch, per-block BN partials --------
template <int F>
__device__ __forceinline__ void conv_body(const float* __restrict__ x,
                                          const float* __restrict__ cw,
                                          const float* __restrict__ cb,
                                          int o, int b, int br) {
    const int pad = F / 2;
    __shared__ float wsh[H * F];
    int tid = threadIdx.x;
    if (tid < H * F) wsh[tid] = cw[o * (H * F) + tid];
    __syncthreads();

    int l0 = tid * 4;
    float bias = __ldg(cb + o);
    float acc[4];
#pragma unroll
    for (int j = 0; j < 4; j++) acc[j] = bias;

    const float* xb = x + b * (H * L);
#pragma unroll
    for (int i = 0; i < H; i++) {
        float xr[4 + F - 1];
#pragma unroll
        for (int m = 0; m < 4 + F - 1; m++) {
            int li = l0 + m - pad;
            xr[m] = (li >= 0 && li < L) ? xb[i * L + li] : 0.0f;
        }
#pragma unroll
        for (int f = 0; f < F; f++) {
            float wv = wsh[i * F + f];
#pragma unroll
            for (int j = 0; j < 4; j++) acc[j] += xr[j + f] * wv;
        }
    }

    float s1 = 0.0f, s2 = 0.0f;
#pragma unroll
    for (int j = 0; j < 4; j++) {
        g_y[br][b * (H * L) + o * L + l0 + j] = acc[j];
        s1 += acc[j];
        s2 += acc[j] * acc[j];
    }
#pragma unroll
    for (int off = 16; off; off >>= 1) {
        s1 += __shfl_down_sync(0xffffffffu, s1, off);
        s2 += __shfl_down_sync(0xffffffffu, s2, off);
    }
    __shared__ float red1[8], red2[8];
    int wi = tid >> 5, ln = tid & 31;
    if (ln == 0) { red1[wi] = s1; red2[wi] = s2; }
    __syncthreads();
    if (tid == 0) {
        float t1 = 0.0f, t2 = 0.0f;
#pragma unroll
        for (int i = 0; i < 8; i++) { t1 += red1[i]; t2 += red2[i]; }
        g_part[br][o][b] = make_float2(t1, t2);
    }
}

__global__ void k2_conv_all(const float* __restrict__ cq3w, const float* __restrict__ cq3b,
                            const float* __restrict__ cq9w, const float* __restrict__ cq9b,
                            const float* __restrict__ ck3w, const float* __restrict__ ck3b,
                            const float* __restrict__ ck9w, const float* __restrict__ ck9b) {
    int o = blockIdx.x, b = blockIdx.y, br = blockIdx.z;
    const float* x = (br < 2) ? g_Qp : g_Kp;
    switch (br) {
        case 0: conv_body<3>(x, cq3w, cq3b, o, b, 0); break;
        case 1: conv_body<9>(x, cq9w, cq9b, o, b, 1); break;
        case 2: conv_body<3>(x, ck3w, ck3b, o, b, 2); break;
        default: conv_body<9>(x, ck9w, ck9b, o, b, 3); break;
    }
}

// -------- K3: finalize BN affine from partials, compute c = dot(wbq,wbk)/8 --------
__global__ void k3_final(const float* __restrict__ g0, const float* __restrict__ be0,
                         const float* __restrict__ g1, const float* __restrict__ be1,
                         const float* __restrict__ g2, const float* __restrict__ be2,
                         const float* __restrict__ g3, const float* __restrict__ be3,
                         const float* __restrict__ wbq, const float* __restrict__ wbk) {
    int t = threadIdx.x;
    if (t < 32) {
        int br = t >> 3, o = t & 7;
        const float* gg;
        const float* bb;
        if (br == 0) { gg = g0; bb = be0; }
        else if (br == 1) { gg = g1; bb = be1; }
        else if (br == 2) { gg = g2; bb = be2; }
        else { gg = g3; bb = be3; }
        float s1 = 0.0f, s2 = 0.0f;
#pragma unroll
        for (int b = 0; b < BATCH; b++) {
            float2 p = g_part[br][o][b];
            s1 += p.x;
            s2 += p.y;
        }
        float n = (float)(BATCH * L);
        float mu = s1 / n;
        float var = s2 / n - mu * mu;
        float sc = gg[o] / sqrtf(var + 1e-5f);
        g_scale[br][o] = sc;
        g_shift[br][o] = bb[o] - mu * sc;
    }
    if (t == 32) {
        float s = 0.0f;
        for (int d = 0; d < DK; d++) s += wbq[d] * wbk[d];
        g_cscale = s * 0.125f;  // 1/sqrt(64)
    }
}

// -------- K4: fused BN-affine + softmax + cat/reshape-max --------
// Qm[bh][l], bh<32: pairwise max of adjacent elems of branch0 rows (2bh, 2bh+1)
//            bh>=32: same on branch1 rows (2(bh-32), 2(bh-32)+1)
// grid (r=32, half=2, qk=2); 1024 threads: warps 0-15 -> srcrow 2r, warps 16-31 -> 2r+1
__global__ void k4_smmax() {
    int r = blockIdx.x, half = blockIdx.y, qk = blockIdx.z;
    int br = qk * 2 + half;
    int tid = threadIdx.x;
    int row01 = tid >> 9, j = tid & 511;
    int srcrow = 2 * r + row01;
    int o = srcrow & 7;
    float sc = g_scale[br][o], sh = g_shift[br][o];
    const float2* y2 = (const float2*)&g_y[br][srcrow * L];
    float2 yv = y2[j];
    float v0 = yv.x * sc + sh;
    float v1 = yv.y * sc + sh;

    __shared__ float red[32];
    float m = fmaxf(v0, v1);
#pragma unroll
    for (int off = 16; off; off >>= 1) m = fmaxf(m, __shfl_xor_sync(0xffffffffu, m, off));
    int w = tid >> 5, ln = tid & 31;
    if (ln == 0) red[w] = m;
    __syncthreads();
    float mx = -1e30f;
#pragma unroll
    for (int i = 0; i < 16; i++) mx = fmaxf(mx, red[row01 * 16 + i]);
    __syncthreads();

    float e0 = __expf(v0 - mx), e1 = __expf(v1 - mx);
    float s = e0 + e1;
#pragma unroll
    for (int off = 16; off; off >>= 1) s += __shfl_xor_sync(0xffffffffu, s, off);
    if (ln == 0) red[w] = s;
    __syncthreads();
    float tot = 0.0f;
#pragma unroll
    for (int i = 0; i < 16; i++) tot += red[row01 * 16 + i];
    float inv = 1.0f / tot;

    float* dst = qk ? g_Km : g_Qm;
    dst[(half * 32 + r) * L + row01 * 512 + j] = fmaxf(e0, e1) * inv;
}

// -------- K5: moment partials M_t[d] = sum_k Km[k]^t V[k,d] / t!  (4-way k-split) --------
// grid (bh=64, ks=4); 256 threads = 4 k-groups x 64 d; each thread 64 serial k
__global__ void k5_moments(const float* __restrict__ V) {
    int bh = blockIdx.x, ks = blockIdx.y;
    int tid = threadIdx.x;
    int kg = tid >> 6, d = tid & 63;
    float acc[NT];
#pragma unroll
    for (int t = 0; t < NT; t++) acc[t] = 0.0f;
    const float* vb = V + (size_t)bh * L * DK;
    const float* km = g_Km + bh * L;
    int kbase = ks * 256 + kg * 64;
#pragma unroll 4
    for (int jj = 0; jj < 64; jj++) {
        int k = kbase + jj;
        float kv = __ldg(km + k);
        float v = vb[(size_t)k * DK + d];
        float kv2 = kv * kv;
        float pe = v, po = v * kv;
        acc[0] += pe;
        acc[1] += po;
#pragma unroll
        for (int t = 2; t < NT; t += 2) {
            pe *= kv2;
            acc[t] += pe;
            if (t + 1 < NT) {
                po *= kv2;
                acc[t + 1] += po;
            }
        }
    }
    __shared__ float red[4][NT][DK];
#pragma unroll
    for (int t = 0; t < NT; t++) red[kg][t][d] = acc[t];
    __syncthreads();
    if (kg == 0) {
#pragma unroll
        for (int t = 0; t < NT; t++) {
            float s = red[0][t][d] + red[1][t][d] + red[2][t][d] + red[3][t][d];
            g_Mp[ks][bh][t * DK + d] = s * c_invfact[t];
        }
    }
}

// -------- K6: attn rows (exp + normalize + store) and context via Horner --------
// grid (qc=16, bh=64); 256 threads = 8 warps; each warp 8 q rows (64 rows/block)
__global__ void __launch_bounds__(256) k6_main(float* __restrict__ out) {
    int bh = blockIdx.y;
    int tid = threadIdx.x;
    __shared__ float sKm[L];
    __shared__ float sM[NT * DK];
    for (int i = tid; i < L; i += 256) sKm[i] = g_Km[bh * L + i];
    for (int i = tid; i < NT * DK; i += 256)
        sM[i] = (g_Mp[0][bh][i] + g_Mp[1][bh][i]) + (g_Mp[2][bh][i] + g_Mp[3][bh][i]);
    __syncthreads();

    int wi = tid >> 5, lane = tid & 31;
    float cs = g_cscale;
    const float* qmrow = g_Qm + bh * L;

#pragma unroll 1
    for (int rr = 0; rr < 8; rr++) {
        int q = blockIdx.x * 64 + wi * 8 + rr;
        float a = __ldg(qmrow + q) * cs;

        float E[8][4];
        float z = 0.0f;
#pragma unroll
        for (int j = 0; j < 8; j++) {
            float4 kmv = ((const float4*)sKm)[j * 32 + lane];
            E[j][0] = __expf(a * kmv.x);
            E[j][1] = __expf(a * kmv.y);
            E[j][2] = __expf(a * kmv.z);
            E[j][3] = __expf(a * kmv.w);
            z += (E[j][0] + E[j][1]) + (E[j][2] + E[j][3]);
        }
#pragma unroll
        for (int off = 16; off; off >>= 1) z += __shfl_xor_sync(0xffffffffu, z, off);
        float invz = 1.0f / z;

        float* attn = out + CTX_ELEMS + ((size_t)bh * L + q) * L;
#pragma unroll
        for (int j = 0; j < 8; j++) {
            float4 o4;
            o4.x = E[j][0] * invz;
            o4.y = E[j][1] * invz;
            o4.z = E[j][2] * invz;
            o4.w = E[j][3] * invz;
            ((float4*)attn)[j * 32 + lane] = o4;
        }

        float* ctx = out + ((size_t)bh * L + q) * DK;
#pragma unroll
        for (int dd = 0; dd < 2; dd++) {
            int d = lane + dd * 32;
            float num = sM[TTERMS * DK + d];
#pragma unroll
            for (int t = TTERMS - 1; t >= 0; t--) num = num * a + sM[t * DK + d];
            ctx[d] = num * invz;
        }
    }
}

extern "C" void kernel_launch(void* const* d_in, const int* in_sizes, int n_in,
                              void* d_out, int out_size) {
    (void)in_sizes;
    (void)n_in;
    (void)out_size;
    const float* Q = (const float*)d_in[0];
    const float* K = (const float*)d_in[1];
    const float* V = (const float*)d_in[2];
    // d_in[3] = attn_mask (unused, faithful to reference)
    const float* wq = (const float*)d_in[4];
    const float* wk = (const float*)d_in[5];
    const float* wbq = (const float*)d_in[6];
    const float* wbk = (const float*)d_in[7];
    const float* cq3_w = (const float*)d_in[8];
    const float* cq3_b = (const float*)d_in[9];
    const float* cq9_w = (const float*)d_in[10];
    const float* cq9_b = (const float*)d_in[11];
    const float* ck3_w = (const float*)d_in[12];
    const float* ck3_b = (const float*)d_in[13];
    const float* ck9_w = (const float*)d_in[14];
    const float* ck9_b = (const float*)d_in[15];
    const float* bnq3_g = (const float*)d_in[16];
    const float* bnq3_b = (const float*)d_in[17];
    const float* bnq9_g = (const float*)d_in[18];
    const float* bnq9_b = (const float*)d_in[19];
    const float* bnk3_g = (const float*)d_in[20];
    const float* bnk3_b = (const float*)d_in[21];
    const float* bnk9_g = (const float*)d_in[22];
    const float* bnk9_b = (const float*)d_in[23];
    float* out = (float*)d_out;

    k1_proj<<<(2 * NPOS) / 8, 256>>>(Q, K, wq, wk);
    k2_conv_all<<<dim3(8, 8, 4), 256>>>(cq3_w, cq3_b, cq9_w, cq9_b,
                                        ck3_w, ck3_b, ck9_w, ck9_b);
    k3_final<<<1, 64>>>(bnq3_g, bnq3_b, bnq9_g, bnq9_b,
                        bnk3_g, bnk3_b, bnk9_g, bnk9_b, wbq, wbk);
    k4_smmax<<<dim3(32, 2, 2), 1024>>>();
    k5_moments<<<dim3(BH, 4), 256>>>(V);
    k6_main<<<dim3(16, BH), 256>>>(out);
}

// round 8
// speedup vs baseline: 1.6620x; 1.0754x over previous
#include <cuda_runtime.h>

#define BATCH 8
#define H 8
#define L 1024
#define DK 64
#define BH 64            // BATCH*H
#define NPOS 65536       // BH*L
#define TTERMS 12
#define NT (TTERMS + 1)
#define CTX_ELEMS (BH * L * DK)   // 4194304

// -------- scratch (device globals; no runtime allocation) --------
__device__ float g_Qp[NPOS];
__device__ float g_Kp[NPOS];
__device__ float g_y[4][NPOS];
__device__ float2 g_part[4][H][BATCH];   // per-block BN partials (no atomics)
__device__ float g_Qm[NPOS];
__device__ float g_Km[NPOS];
__device__ float g_M[BH][NT * DK];       // final moments (incl 1/t!)
__device__ float g_cscale;

__constant__ float c_invfact[NT] = {
    1.0f, 1.0f, 0.5f, 1.0f / 6.0f, 1.0f / 24.0f, 1.0f / 120.0f,
    1.0f / 720.0f, 1.0f / 5040.0f, 1.0f / 40320.0f, 1.0f / 362880.0f,
    1.0f / 3628800.0f, 1.0f / 39916800.0f, 1.0f / 479001600.0f};

// -------- K1: Qp = Q . wq, Kp = K . wk (warp per output) --------
__global__ void k1_proj(const float* __restrict__ Q, const float* __restrict__ K,
                        const float* __restrict__ wq, const float* __restrict__ wk) {
    int warp = (blockIdx.x * blockDim.x + threadIdx.x) >> 5;
    int lane = threadIdx.x & 31;
    const float* src;
    const float* w;
    float* dst;
    int i;
    if (warp < NPOS) { src = Q; w = wq; dst = g_Qp; i = warp; }
    else             { src = K; w = wk; dst = g_Kp; i = warp - NPOS; }
    const float* p = src + (size_t)i * DK;
    float s = p[lane] * __ldg(w + lane) + p[lane + 32] * __ldg(w + lane + 32);
#pragma unroll
    for (int off = 16; off; off >>= 1) s += __shfl_down_sync(0xffffffffu, s, off);
    if (lane == 0) dst[i] = s;
}

// -------- K2: all 4 Conv1d branches in one launch, per-block BN partials --------
template <int F>
__device__ __forceinline__ void conv_body(const float* __restrict__ x,
                                          const float* __restrict__ cw,
                                          const float* __restrict__ cb,
                                          int o, int b, int br) {
    const int pad = F / 2;
    __shared__ float wsh[H * F];
    int tid = threadIdx.x;
    if (tid < H * F) wsh[tid] = cw[o * (H * F) + tid];
    __syncthreads();

    int l0 = tid * 4;
    float bias = __ldg(cb + o);
    float acc[4];
#pragma unroll
    for (int j = 0; j < 4; j++) acc[j] = bias;

    const float* xb = x + b * (H * L);
#pragma unroll
    for (int i = 0; i < H; i++) {
        float xr[4 + F - 1];
#pragma unroll
        for (int m = 0; m < 4 + F - 1; m++) {
            int li = l0 + m - pad;
            xr[m] = (li >= 0 && li < L) ? xb[i * L + li] : 0.0f;
        }
#pragma unroll
        for (int f = 0; f < F; f++) {
            float wv = wsh[i * F + f];
#pragma unroll
            for (int j = 0; j < 4; j++) acc[j] += xr[j + f] * wv;
        }
    }

    float s1 = 0.0f, s2 = 0.0f;
#pragma unroll
    for (int j = 0; j < 4; j++) {
        g_y[br][b * (H * L) + o * L + l0 + j] = acc[j];
        s1 += acc[j];
        s2 += acc[j] * acc[j];
    }
#pragma unroll
    for (int off = 16; off; off >>= 1) {
        s1 += __shfl_down_sync(0xffffffffu, s1, off);
        s2 += __shfl_down_sync(0xffffffffu, s2, off);
    }
    __shared__ float red1[8], red2[8];
    int wi = tid >> 5, ln = tid & 31;
    if (ln == 0) { red1[wi] = s1; red2[wi] = s2; }
    __syncthreads();
    if (tid == 0) {
        float t1 = 0.0f, t2 = 0.0f;
#pragma unroll
        for (int i = 0; i < 8; i++) { t1 += red1[i]; t2 += red2[i]; }
        g_part[br][o][b] = make_float2(t1, t2);
    }
}

__global__ void k2_conv_all(const float* __restrict__ cq3w, const float* __restrict__ cq3b,
                            const float* __restrict__ cq9w, const float* __restrict__ cq9b,
                            const float* __restrict__ ck3w, const float* __restrict__ ck3b,
                            const float* __restrict__ ck9w, const float* __restrict__ ck9b) {
    int o = blockIdx.x, b = blockIdx.y, br = blockIdx.z;
    const float* x = (br < 2) ? g_Qp : g_Kp;
    switch (br) {
        case 0: conv_body<3>(x, cq3w, cq3b, o, b, 0); break;
        case 1: conv_body<9>(x, cq9w, cq9b, o, b, 1); break;
        case 2: conv_body<3>(x, ck3w, ck3b, o, b, 2); break;
        default: conv_body<9>(x, ck9w, ck9b, o, b, 3); break;
    }
}

// -------- K45: fused BN-affine + softmax + cat/reshape-max + moments --------
// grid (r=32, half=2, qk=2); 1024 threads.
// Output row (half*32+r) of Qm (qk=0) / Km (qk=1), then for qk=1 the same block
// computes final moments M_t[d] = sum_k Km[k]^t V[k,d] / t! for bh = half*32+r.
__global__ void __launch_bounds__(1024) k45_smmax_mom(
    const float* __restrict__ V,
    const float* __restrict__ wbq, const float* __restrict__ wbk,
    const float* __restrict__ g0, const float* __restrict__ be0,
    const float* __restrict__ g1, const float* __restrict__ be1,
    const float* __restrict__ g2, const float* __restrict__ be2,
    const float* __restrict__ g3, const float* __restrict__ be3) {
    int r = blockIdx.x, half = blockIdx.y, qk = blockIdx.z;
    int br = qk * 2 + half;
    int tid = threadIdx.x;
    int row01 = tid >> 9, j = tid & 511;
    int srcrow = 2 * r + row01;
    int o = srcrow & 7;

    // BN affine inline from partials
    const float* gg;
    const float* bb;
    if (br == 0) { gg = g0; bb = be0; }
    else if (br == 1) { gg = g1; bb = be1; }
    else if (br == 2) { gg = g2; bb = be2; }
    else { gg = g3; bb = be3; }
    float s1 = 0.0f, s2 = 0.0f;
#pragma unroll
    for (int b = 0; b < BATCH; b++) {
        float2 p = g_part[br][o][b];
        s1 += p.x;
        s2 += p.y;
    }
    float n = (float)(BATCH * L);
    float mu = s1 / n;
    float var = s2 / n - mu * mu;
    float sc = __ldg(gg + o) / sqrtf(var + 1e-5f);
    float sh = __ldg(bb + o) - mu * sc;

    const float2* y2 = (const float2*)&g_y[br][srcrow * L];
    float2 yv = y2[j];
    float v0 = yv.x * sc + sh;
    float v1 = yv.y * sc + sh;

    __shared__ float red[32];
    __shared__ float sKm[L];
    float m = fmaxf(v0, v1);
#pragma unroll
    for (int off = 16; off; off >>= 1) m = fmaxf(m, __shfl_xor_sync(0xffffffffu, m, off));
    int w = tid >> 5, ln = tid & 31;
    if (ln == 0) red[w] = m;
    __syncthreads();
    float mx = -1e30f;
#pragma unroll
    for (int i = 0; i < 16; i++) mx = fmaxf(mx, red[row01 * 16 + i]);
    __syncthreads();

    float e0 = __expf(v0 - mx), e1 = __expf(v1 - mx);
    float ss = e0 + e1;
#pragma unroll
    for (int off = 16; off; off >>= 1) ss += __shfl_xor_sync(0xffffffffu, ss, off);
    if (ln == 0) red[w] = ss;
    __syncthreads();
    float tot = 0.0f;
#pragma unroll
    for (int i = 0; i < 16; i++) tot += red[row01 * 16 + i];
    float val = fmaxf(e0, e1) / tot;

    int outrow = half * 32 + r;
    int outpos = row01 * 512 + j;
    float* dst = qk ? g_Km : g_Qm;
    dst[outrow * L + outpos] = val;

    if (qk == 0) {
        // one designated block also computes cscale
        if (r == 0 && half == 0 && tid == 0) {
            float s = 0.0f;
            for (int d = 0; d < DK; d++) s += wbq[d] * wbk[d];
            g_cscale = s * 0.125f;  // 1/sqrt(64)
        }
        return;
    }

    // ---- moments for bh = outrow (Km row is in this block) ----
    sKm[outpos] = val;
    __syncthreads();

    int bh = outrow;
    int kg = tid >> 6, d = tid & 63;   // 16 k-groups x 64 d
    float acc[NT];
#pragma unroll
    for (int t = 0; t < NT; t++) acc[t] = 0.0f;
    const float* vb = V + (size_t)bh * L * DK;
    int kbase = kg * 64;
#pragma unroll 4
    for (int jj = 0; jj < 64; jj++) {
        int k = kbase + jj;
        float kv = sKm[k];
        float v = __ldg(vb + (size_t)k * DK + d);
        float kv2 = kv * kv;
        float pe = v, po = v * kv;
        acc[0] += pe;
        acc[1] += po;
#pragma unroll
        for (int t = 2; t < NT; t += 2) {
            pe *= kv2;
            acc[t] += pe;
            if (t + 1 < NT) {
                po *= kv2;
                acc[t + 1] += po;
            }
        }
    }
    __shared__ float mred[8][NT][DK];   // 26.6 KB
    if (kg >= 8) {
#pragma unroll
        for (int t = 0; t < NT; t++) mred[kg - 8][t][d] = acc[t];
    }
    __syncthreads();
    if (kg < 8) {
#pragma unroll
        for (int t = 0; t < NT; t++) mred[kg][t][d] += acc[t];
    }
    __syncthreads();
    if (tid < NT * DK) {
        int t = tid >> 6, dd = tid & 63;
        float s = 0.0f;
#pragma unroll
        for (int g = 0; g < 8; g++) s += mred[g][t][dd];
        g_M[bh][t * DK + dd] = s * c_invfact[t];
    }
}

// -------- K6: attn rows (exp + normalize + store) and context via Horner --------
// grid (qc=16, bh=64); 256 threads = 8 warps; each warp 8 q rows (64 rows/block)
__global__ void __launch_bounds__(256) k6_main(float* __restrict__ out) {
    int bh = blockIdx.y;
    int tid = threadIdx.x;
    __shared__ float sKm[L];
    __shared__ float sM[NT * DK];
    for (int i = tid; i < L; i += 256) sKm[i] = g_Km[bh * L + i];
    for (int i = tid; i < NT * DK; i += 256) sM[i] = g_M[bh][i];
    __syncthreads();

    int wi = tid >> 5, lane = tid & 31;
    float cs = g_cscale;
    const float* qmrow = g_Qm + bh * L;

#pragma unroll 1
    for (int rr = 0; rr < 8; rr++) {
        int q = blockIdx.x * 64 + wi * 8 + rr;
        float a = __ldg(qmrow + q) * cs;

        float E[8][4];
        float z = 0.0f;
#pragma unroll
        for (int j = 0; j < 8; j++) {
            float4 kmv = ((const float4*)sKm)[j * 32 + lane];
            E[j][0] = __expf(a * kmv.x);
            E[j][1] = __expf(a * kmv.y);
            E[j][2] = __expf(a * kmv.z);
            E[j][3] = __expf(a * kmv.w);
            z += (E[j][0] + E[j][1]) + (E[j][2] + E[j][3]);
        }
#pragma unroll
        for (int off = 16; off; off >>= 1) z += __shfl_xor_sync(0xffffffffu, z, off);
        float invz = 1.0f / z;

        float* attn = out + CTX_ELEMS + ((size_t)bh * L + q) * L;
#pragma unroll
        for (int j = 0; j < 8; j++) {
            float4 o4;
            o4.x = E[j][0] * invz;
            o4.y = E[j][1] * invz;
            o4.z = E[j][2] * invz;
            o4.w = E[j][3] * invz;
            __stcs(((float4*)attn) + j * 32 + lane, o4);
        }

        float* ctx = out + ((size_t)bh * L + q) * DK;
#pragma unroll
        for (int dd = 0; dd < 2; dd++) {
            int d = lane + dd * 32;
            float num = sM[TTERMS * DK + d];
#pragma unroll
            for (int t = TTERMS - 1; t >= 0; t--) num = num * a + sM[t * DK + d];
            ctx[d] = num * invz;
        }
    }
}

extern "C" void kernel_launch(void* const* d_in, const int* in_sizes, int n_in,
                              void* d_out, int out_size) {
    (void)in_sizes;
    (void)n_in;
    (void)out_size;
    const float* Q = (const float*)d_in[0];
    const float* K = (const float*)d_in[1];
    const float* V = (const float*)d_in[2];
    // d_in[3] = attn_mask (unused, faithful to reference)
    const float* wq = (const float*)d_in[4];
    const float* wk = (const float*)d_in[5];
    const float* wbq = (const float*)d_in[6];
    const float* wbk = (const float*)d_in[7];
    const float* cq3_w = (const float*)d_in[8];
    const float* cq3_b = (const float*)d_in[9];
    const float* cq9_w = (const float*)d_in[10];
    const float* cq9_b = (const float*)d_in[11];
    const float* ck3_w = (const float*)d_in[12];
    const float* ck3_b = (const float*)d_in[13];
    const float* ck9_w = (const float*)d_in[14];
    const float* ck9_b = (const float*)d_in[15];
    const float* bnq3_g = (const float*)d_in[16];
    const float* bnq3_b = (const float*)d_in[17];
    const float* bnq9_g = (const float*)d_in[18];
    const float* bnq9_b = (const float*)d_in[19];
    const float* bnk3_g = (const float*)d_in[20];
    const float* bnk3_b = (const float*)d_in[21];
    const float* bnk9_g = (const float*)d_in[22];
    const float* bnk9_b = (const float*)d_in[23];
    float* out = (float*)d_out;

    k1_proj<<<(2 * NPOS) / 8, 256>>>(Q, K, wq, wk);
    k2_conv_all<<<dim3(8, 8, 4), 256>>>(cq3_w, cq3_b, cq9_w, cq9_b,
                                        ck3_w, ck3_b, ck9_w, ck9_b);
    k45_smmax_mom<<<dim3(32, 2, 2), 1024>>>(V, wbq, wbk,
                                            bnq3_g, bnq3_b, bnq9_g, bnq9_b,
                                            bnk3_g, bnk3_b, bnk9_g, bnk9_b);
    k6_main<<<dim3(16, BH), 256>>>(out);
}

// round 9
// speedup vs baseline: 1.9233x; 1.1572x over previous
#include <cuda_runtime.h>

#define BATCH 8
#define H 8
#define L 1024
#define DK 64
#define BH 64            // BATCH*H
#define NPOS 65536       // BH*L
#define TTERMS 12
#define NT (TTERMS + 1)
#define CTX_ELEMS (BH * L * DK)   // 4194304

// -------- scratch (device globals; no runtime allocation) --------
__device__ float g_Qp[NPOS];
__device__ float g_Kp[NPOS];
__device__ float g_y[4][NPOS];
__device__ float2 g_part[4][H][BATCH];   // per-block BN partials (no atomics)
__device__ float g_Qm[NPOS];
__device__ float g_Km[NPOS];
__device__ float g_M[BH][NT * DK];       // final V-moments (incl 1/t!)
__device__ float g_Z[BH][NT];            // final Z-moments (incl 1/t!)
__device__ float g_cscale;

__constant__ float c_invfact[NT] = {
    1.0f, 1.0f, 0.5f, 1.0f / 6.0f, 1.0f / 24.0f, 1.0f / 120.0f,
    1.0f / 720.0f, 1.0f / 5040.0f, 1.0f / 40320.0f, 1.0f / 362880.0f,
    1.0f / 3628800.0f, 1.0f / 39916800.0f, 1.0f / 479001600.0f};

// -------- K1: Qp = Q . wq, Kp = K . wk (16 lanes per row, float4) --------
__global__ void k1_proj(const float* __restrict__ Q, const float* __restrict__ K,
                        const float* __restrict__ wq, const float* __restrict__ wk) {
    int gtid = blockIdx.x * blockDim.x + threadIdx.x;
    int warp = gtid >> 5;
    int lane = threadIdx.x & 31;
    int row = warp * 2 + (lane >> 4);   // 2 rows per warp; both on same side of NPOS
    int l16 = lane & 15;
    const float* src;
    const float* w;
    float* dst;
    int i;
    if (row < NPOS) { src = Q; w = wq; dst = g_Qp; i = row; }
    else            { src = K; w = wk; dst = g_Kp; i = row - NPOS; }
    float4 p = ((const float4*)(src + (size_t)i * DK))[l16];
    float4 wv = __ldg(((const float4*)w) + l16);
    float s = p.x * wv.x + p.y * wv.y + p.z * wv.z + p.w * wv.w;
#pragma unroll
    for (int off = 8; off; off >>= 1) s += __shfl_down_sync(0xffffffffu, s, off, 16);
    if (l16 == 0) dst[i] = s;
}

// -------- K2: all 4 Conv1d branches in one launch, per-block BN partials --------
template <int F>
__device__ __forceinline__ void conv_body(const float* __restrict__ x,
                                          const float* __restrict__ cw,
                                          const float* __restrict__ cb,
                                          int o, int b, int br) {
    const int pad = F / 2;
    __shared__ float wsh[H * F];
    int tid = threadIdx.x;
    if (tid < H * F) wsh[tid] = cw[o * (H * F) + tid];
    __syncthreads();

    int l0 = tid * 4;
    float bias = __ldg(cb + o);
    float acc[4];
#pragma unroll
    for (int j = 0; j < 4; j++) acc[j] = bias;

    const float* xb = x + b * (H * L);
#pragma unroll
    for (int i = 0; i < H; i++) {
        float xr[4 + F - 1];
#pragma unroll
        for (int m = 0; m < 4 + F - 1; m++) {
            int li = l0 + m - pad;
            xr[m] = (li >= 0 && li < L) ? xb[i * L + li] : 0.0f;
        }
#pragma unroll
        for (int f = 0; f < F; f++) {
            float wv = wsh[i * F + f];
#pragma unroll
            for (int j = 0; j < 4; j++) acc[j] += xr[j + f] * wv;
        }
    }

    float s1 = 0.0f, s2 = 0.0f;
#pragma unroll
    for (int j = 0; j < 4; j++) {
        g_y[br][b * (H * L) + o * L + l0 + j] = acc[j];
        s1 += acc[j];
        s2 += acc[j] * acc[j];
    }
#pragma unroll
    for (int off = 16; off; off >>= 1) {
        s1 += __shfl_down_sync(0xffffffffu, s1, off);
        s2 += __shfl_down_sync(0xffffffffu, s2, off);
    }
    __shared__ float red1[8], red2[8];
    int wi = tid >> 5, ln = tid & 31;
    if (ln == 0) { red1[wi] = s1; red2[wi] = s2; }
    __syncthreads();
    if (tid == 0) {
        float t1 = 0.0f, t2 = 0.0f;
#pragma unroll
        for (int i = 0; i < 8; i++) { t1 += red1[i]; t2 += red2[i]; }
        g_part[br][o][b] = make_float2(t1, t2);
    }
}

__global__ void k2_conv_all(const float* __restrict__ cq3w, const float* __restrict__ cq3b,
                            const float* __restrict__ cq9w, const float* __restrict__ cq9b,
                            const float* __restrict__ ck3w, const float* __restrict__ ck3b,
                            const float* __restrict__ ck9w, const float* __restrict__ ck9b) {
    int o = blockIdx.x, b = blockIdx.y, br = blockIdx.z;
    const float* x = (br < 2) ? g_Qp : g_Kp;
    switch (br) {
        case 0: conv_body<3>(x, cq3w, cq3b, o, b, 0); break;
        case 1: conv_body<9>(x, cq9w, cq9b, o, b, 1); break;
        case 2: conv_body<3>(x, ck3w, ck3b, o, b, 2); break;
        default: conv_body<9>(x, ck9w, ck9b, o, b, 3); break;
    }
}

// -------- K45: fused BN-affine + softmax + cat/reshape-max + moments --------
// grid (r=32, half=2, qk=2); 1024 threads.
__global__ void __launch_bounds__(1024) k45_smmax_mom(
    const float* __restrict__ V,
    const float* __restrict__ wbq, const float* __restrict__ wbk,
    const float* __restrict__ g0, const float* __restrict__ be0,
    const float* __restrict__ g1, const float* __restrict__ be1,
    const float* __restrict__ g2, const float* __restrict__ be2,
    const float* __restrict__ g3, const float* __restrict__ be3) {
    int r = blockIdx.x, half = blockIdx.y, qk = blockIdx.z;
    int br = qk * 2 + half;
    int tid = threadIdx.x;
    int row01 = tid >> 9, j = tid & 511;
    int srcrow = 2 * r + row01;
    int o = srcrow & 7;

    // BN affine inline from partials
    const float* gg;
    const float* bb;
    if (br == 0) { gg = g0; bb = be0; }
    else if (br == 1) { gg = g1; bb = be1; }
    else if (br == 2) { gg = g2; bb = be2; }
    else { gg = g3; bb = be3; }
    float s1 = 0.0f, s2 = 0.0f;
#pragma unroll
    for (int b = 0; b < BATCH; b++) {
        float2 p = g_part[br][o][b];
        s1 += p.x;
        s2 += p.y;
    }
    float n = (float)(BATCH * L);
    float mu = s1 / n;
    float var = s2 / n - mu * mu;
    float sc = __ldg(gg + o) / sqrtf(var + 1e-5f);
    float sh = __ldg(bb + o) - mu * sc;

    const float2* y2 = (const float2*)&g_y[br][srcrow * L];
    float2 yv = y2[j];
    float v0 = yv.x * sc + sh;
    float v1 = yv.y * sc + sh;

    __shared__ float red[32];
    __shared__ float sKm[L];
    float m = fmaxf(v0, v1);
#pragma unroll
    for (int off = 16; off; off >>= 1) m = fmaxf(m, __shfl_xor_sync(0xffffffffu, m, off));
    int w = tid >> 5, ln = tid & 31;
    if (ln == 0) red[w] = m;
    __syncthreads();
    float mx = -1e30f;
#pragma unroll
    for (int i = 0; i < 16; i++) mx = fmaxf(mx, red[row01 * 16 + i]);
    __syncthreads();

    float e0 = __expf(v0 - mx), e1 = __expf(v1 - mx);
    float ss = e0 + e1;
#pragma unroll
    for (int off = 16; off; off >>= 1) ss += __shfl_xor_sync(0xffffffffu, ss, off);
    if (ln == 0) red[w] = ss;
    __syncthreads();
    float tot = 0.0f;
#pragma unroll
    for (int i = 0; i < 16; i++) tot += red[row01 * 16 + i];
    float val = fmaxf(e0, e1) / tot;

    int outrow = half * 32 + r;
    int outpos = row01 * 512 + j;
    float* dst = qk ? g_Km : g_Qm;
    dst[outrow * L + outpos] = val;

    if (qk == 0) {
        if (r == 0 && half == 0 && tid == 0) {
            float s = 0.0f;
            for (int d = 0; d < DK; d++) s += wbq[d] * wbk[d];
            g_cscale = s * 0.125f;  // 1/sqrt(64)
        }
        return;
    }

    // ---- moments for bh = outrow (Km row is in this block) ----
    sKm[outpos] = val;
    __syncthreads();

    int bh = outrow;
    int kg = tid >> 6, d = tid & 63;   // 16 k-groups x 64 d
    float acc[NT];
#pragma unroll
    for (int t = 0; t < NT; t++) acc[t] = 0.0f;
    const float* vb = V + (size_t)bh * L * DK;
    int kbase = kg * 64;
#pragma unroll 4
    for (int jj = 0; jj < 64; jj++) {
        int k = kbase + jj;
        float kv = sKm[k];
        float v = __ldg(vb + (size_t)k * DK + d);
        float kv2 = kv * kv;
        float pe = v, po = v * kv;
        acc[0] += pe;
        acc[1] += po;
#pragma unroll
        for (int t = 2; t < NT; t += 2) {
            pe *= kv2;
            acc[t] += pe;
            if (t + 1 < NT) {
                po *= kv2;
                acc[t + 1] += po;
            }
        }
    }
    __shared__ float mred[8][NT][DK];   // 26.6 KB
    __shared__ float zred[16][NT];
    if (kg >= 8) {
#pragma unroll
        for (int t = 0; t < NT; t++) mred[kg - 8][t][d] = acc[t];
    }
    // Z-moments: one lane per k-group accumulates sum_k Km^t
    if (d == 0) {
        float za[NT];
#pragma unroll
        for (int t = 0; t < NT; t++) za[t] = 0.0f;
        for (int jj = 0; jj < 64; jj++) {
            float kv = sKm[kbase + jj];
            float kv2 = kv * kv;
            float pe = 1.0f, po = kv;
            za[0] += pe;
            za[1] += po;
#pragma unroll
            for (int t = 2; t < NT; t += 2) {
                pe *= kv2;
                za[t] += pe;
                if (t + 1 < NT) {
                    po *= kv2;
                    za[t + 1] += po;
                }
            }
        }
#pragma unroll
        for (int t = 0; t < NT; t++) zred[kg][t] = za[t];
    }
    __syncthreads();
    if (kg < 8) {
#pragma unroll
        for (int t = 0; t < NT; t++) mred[kg][t][d] += acc[t];
    }
    __syncthreads();
    if (tid < NT * DK) {
        int t = tid >> 6, dd = tid & 63;
        float s = 0.0f;
#pragma unroll
        for (int g = 0; g < 8; g++) s += mred[g][t][dd];
        g_M[bh][t * DK + dd] = s * c_invfact[t];
    }
    if (tid < NT) {
        float s = 0.0f;
#pragma unroll
        for (int g = 0; g < 16; g++) s += zred[g][tid];
        g_Z[bh][tid] = s * c_invfact[tid];
    }
}

// -------- K6: analytic z, single-pass exp+scale+store, ctx via Horner --------
// grid (qc=16, bh=64); 256 threads = 8 warps; each warp 8 q rows (64 rows/block)
__global__ void __launch_bounds__(256) k6_main(float* __restrict__ out) {
    int bh = blockIdx.y;
    int tid = threadIdx.x;
    __shared__ float sKm[L];
    __shared__ float sM[NT * DK];
    __shared__ float sZ[NT];
    for (int i = tid; i < L; i += 256) sKm[i] = g_Km[bh * L + i];
    for (int i = tid; i < NT * DK; i += 256) sM[i] = g_M[bh][i];
    if (tid < NT) sZ[tid] = g_Z[bh][tid];
    __syncthreads();

    int wi = tid >> 5, lane = tid & 31;
    float cs = g_cscale;
    const float* qmrow = g_Qm + bh * L;

#pragma unroll 1
    for (int rr = 0; rr < 8; rr++) {
        int q = blockIdx.x * 64 + wi * 8 + rr;
        float a = __ldg(qmrow + q) * cs;

        // z = sum_k exp(a*Km_k) analytically (13-term Horner, scalar)
        float z = sZ[TTERMS];
#pragma unroll
        for (int t = TTERMS - 1; t >= 0; t--) z = z * a + sZ[t];
        float invz = 1.0f / z;

        float* attn = out + CTX_ELEMS + ((size_t)bh * L + q) * L;
#pragma unroll
        for (int j = 0; j < 8; j++) {
            float4 kmv = ((const float4*)sKm)[j * 32 + lane];
            float4 o4;
            o4.x = __expf(a * kmv.x) * invz;
            o4.y = __expf(a * kmv.y) * invz;
            o4.z = __expf(a * kmv.z) * invz;
            o4.w = __expf(a * kmv.w) * invz;
            __stcs(((float4*)attn) + j * 32 + lane, o4);
        }

        float* ctx = out + ((size_t)bh * L + q) * DK;
#pragma unroll
        for (int dd = 0; dd < 2; dd++) {
            int d = lane + dd * 32;
            float num = sM[TTERMS * DK + d];
#pragma unroll
            for (int t = TTERMS - 1; t >= 0; t--) num = num * a + sM[t * DK + d];
            ctx[d] = num * invz;
        }
    }
}

extern "C" void kernel_launch(void* const* d_in, const int* in_sizes, int n_in,
                              void* d_out, int out_size) {
    (void)in_sizes;
    (void)n_in;
    (void)out_size;
    const float* Q = (const float*)d_in[0];
    const float* K = (const float*)d_in[1];
    const float* V = (const float*)d_in[2];
    // d_in[3] = attn_mask (unused, faithful to reference)
    const float* wq = (const float*)d_in[4];
    const float* wk = (const float*)d_in[5];
    const float* wbq = (const float*)d_in[6];
    const float* wbk = (const float*)d_in[7];
    const float* cq3_w = (const float*)d_in[8];
    const float* cq3_b = (const float*)d_in[9];
    const float* cq9_w = (const float*)d_in[10];
    const float* cq9_b = (const float*)d_in[11];
    const float* ck3_w = (const float*)d_in[12];
    const float* ck3_b = (const float*)d_in[13];
    const float* ck9_w = (const float*)d_in[14];
    const float* ck9_b = (const float*)d_in[15];
    const float* bnq3_g = (const float*)d_in[16];
    const float* bnq3_b = (const float*)d_in[17];
    const float* bnq9_g = (const float*)d_in[18];
    const float* bnq9_b = (const float*)d_in[19];
    const float* bnk3_g = (const float*)d_in[20];
    const float* bnk3_b = (const float*)d_in[21];
    const float* bnk9_g = (const float*)d_in[22];
    const float* bnk9_b = (const float*)d_in[23];
    float* out = (float*)d_out;

    k1_proj<<<(2 * NPOS) / 8, 256>>>(Q, K, wq, wk);
    k2_conv_all<<<dim3(8, 8, 4), 256>>>(cq3_w, cq3_b, cq9_w, cq9_b,
                                        ck3_w, ck3_b, ck9_w, ck9_b);
    k45_smmax_mom<<<dim3(32, 2, 2), 1024>>>(V, wbq, wbk,
                                            bnq3_g, bnq3_b, bnq9_g, bnq9_b,
                                            bnk3_g, bnk3_b, bnk9_g, bnk9_b);
    k6_main<<<dim3(16, BH), 256>>>(out);
}